// round 3
// baseline (speedup 1.0000x reference)
#include <cuda_runtime.h>

// LIF forward: X [B, T, N] fp32 -> spikes [B, T, N] fp32
// mem_t = (mem_{t-1} + x_t) * 0.5 ; spike = mem > 1 ; mem = spike ? 0 : mem
// Fixed shape: T=32, N=8192.
//
// R3: one float4 column per thread (max thread count = 262144 = 1024 blocks
// of 256), __launch_bounds__(256,7) caps regs at 36 so all 1024 blocks fit
// in ONE wave (148 SMs x 7 blocks = 1036 slots). Full unroll: all 32 load
// addresses are immediate offsets from one base -> ptxas front-batches
// LDG.128s within the reg budget.

#define T_STEPS 32
#define N_DIM   8192
#define N4      (N_DIM / 4)   // 2048 float4 per row
#define ROW_STRIDE N4         // float4 elements between consecutive t

__global__ __launch_bounds__(256, 7)
void lif_kernel3(const float4* __restrict__ X, float4* __restrict__ out,
                 int total_quads) {
    int idx = blockIdx.x * blockDim.x + threadIdx.x;
    if (idx >= total_quads) return;

    int b  = idx >> 11;            // / N4 (N4 = 2048)
    int n4 = idx & (N4 - 1);

    size_t base = (size_t)b * (T_STEPS * N4) + n4;
    const float4* __restrict__ xp = X   + base;
    float4* __restrict__       op = out + base;

    float mx = 0.f, my = 0.f, mz = 0.f, mw = 0.f;

    #pragma unroll
    for (int t = 0; t < T_STEPS; t++) {
        float4 x = xp[t * ROW_STRIDE];

        mx = (mx + x.x) * 0.5f;
        my = (my + x.y) * 0.5f;
        mz = (mz + x.z) * 0.5f;
        mw = (mw + x.w) * 0.5f;

        float4 s;
        s.x = (mx > 1.0f) ? 1.0f : 0.0f;
        s.y = (my > 1.0f) ? 1.0f : 0.0f;
        s.z = (mz > 1.0f) ? 1.0f : 0.0f;
        s.w = (mw > 1.0f) ? 1.0f : 0.0f;

        mx = (mx > 1.0f) ? 0.0f : mx;
        my = (my > 1.0f) ? 0.0f : my;
        mz = (mz > 1.0f) ? 0.0f : mz;
        mw = (mw > 1.0f) ? 0.0f : mw;

        op[t * ROW_STRIDE] = s;
    }
}

extern "C" void kernel_launch(void* const* d_in, const int* in_sizes, int n_in,
                              void* d_out, int out_size) {
    const float4* X = (const float4*)d_in[0];
    float4* out = (float4*)d_out;

    int total_elems = in_sizes[0];                 // B*T*N
    int B = total_elems / (T_STEPS * N_DIM);
    int total_quads = B * N4;

    int threads = 256;
    int blocks = (total_quads + threads - 1) / threads;
    lif_kernel3<<<blocks, threads>>>(X, out, total_quads);
}

// round 4
// speedup vs baseline: 1.0336x; 1.0336x over previous
#include <cuda_runtime.h>

// LIF forward: X [B, T, N] fp32 -> spikes [B, T, N] fp32
// mem_t = (mem_{t-1} + x_t) * 0.5 ; spike = mem > 1 ; mem = spike ? 0 : mem
// Fixed shape: T=32, N=8192.
//
// R4: R3 geometry (1 float4/thread, 1024 blocks x 256, launch_bounds(256,7)
// -> single wave) + __ldcs on input loads. Input is single-use per replay;
// evict-first reads let dirty OUTPUT lines persist in the 126MB L2 across
// graph replays, canceling most write-back DRAM traffic (268MB logical ->
// target ~170MB effective; measured baseline 216MB).

#define T_STEPS 32
#define N_DIM   8192
#define N4      (N_DIM / 4)   // 2048 float4 per row
#define ROW_STRIDE N4

__global__ __launch_bounds__(256, 7)
void lif_kernel4(const float4* __restrict__ X, float4* __restrict__ out,
                 int total_quads) {
    int idx = blockIdx.x * blockDim.x + threadIdx.x;
    if (idx >= total_quads) return;

    int b  = idx >> 11;            // / N4 (N4 = 2048)
    int n4 = idx & (N4 - 1);

    size_t base = (size_t)b * (T_STEPS * N4) + n4;
    const float4* __restrict__ xp = X   + base;
    float4* __restrict__       op = out + base;

    float mx = 0.f, my = 0.f, mz = 0.f, mw = 0.f;

    #pragma unroll
    for (int t = 0; t < T_STEPS; t++) {
        // streaming (evict-first) load: input is never reused this replay,
        // keep L2 capacity for dirty output lines instead.
        float4 x = __ldcs(xp + t * ROW_STRIDE);

        mx = (mx + x.x) * 0.5f;
        my = (my + x.y) * 0.5f;
        mz = (mz + x.z) * 0.5f;
        mw = (mw + x.w) * 0.5f;

        float4 s;
        s.x = (mx > 1.0f) ? 1.0f : 0.0f;
        s.y = (my > 1.0f) ? 1.0f : 0.0f;
        s.z = (mz > 1.0f) ? 1.0f : 0.0f;
        s.w = (mw > 1.0f) ? 1.0f : 0.0f;

        mx = (mx > 1.0f) ? 0.0f : mx;
        my = (my > 1.0f) ? 0.0f : my;
        mz = (mz > 1.0f) ? 0.0f : mz;
        mw = (mw > 1.0f) ? 0.0f : mw;

        // default (write-back, normal priority) store: let dirty lines live
        // in L2 so the next replay overwrites them before eviction.
        op[t * ROW_STRIDE] = s;
    }
}

extern "C" void kernel_launch(void* const* d_in, const int* in_sizes, int n_in,
                              void* d_out, int out_size) {
    const float4* X = (const float4*)d_in[0];
    float4* out = (float4*)d_out;

    int total_elems = in_sizes[0];                 // B*T*N
    int B = total_elems / (T_STEPS * N_DIM);
    int total_quads = B * N4;

    int threads = 256;
    int blocks = (total_quads + threads - 1) / threads;
    lif_kernel4<<<blocks, threads>>>(X, out, total_quads);
}